// round 2
// baseline (speedup 1.0000x reference)
#include <cuda_runtime.h>

#define HH    224
#define WWID  224
#define DCN   64
#define NBAT  8
#define NSC   10
#define CW    8          // owned columns per thread
#define WID   17         // CW + 9 halo columns
#define CHUNK 56         // rows per chunk (4 chunks cover 224)
#define NTILE 28         // 224 / CW
#define NEGF  (-3.0e38f)

// Partial sums: [b][ch][scale], ch = d*8 + c  (matches output layout [B,D,C,10])
__device__ float g_acc[NBAT * DCN * NSC];

__global__ void sgb_zero() {
    int i = blockIdx.x * blockDim.x + threadIdx.x;
    if (i < NBAT * DCN * NSC) g_acc[i] = 0.0f;
}

__global__ void sgb_final(float* __restrict__ out) {
    int i = blockIdx.x * blockDim.x + threadIdx.x;
    if (i < NBAT * DCN * NSC) out[i] = fmaxf(g_acc[i], 0.0f) + 1.0f;
}

// PHASE: 0 = steady (no row masks), 1 = warmup (check h >= i0+t-1), 2 = tail (check h <= i1+t-2)
// EDGE:  column bounds checks needed (last two tiles only)
template<int PHASE, bool EDGE>
__device__ __forceinline__ void row_step(
    const float* __restrict__ prow, const int j0,
    const int i0, const int i1, const int h,
    float* __restrict__ P, float* __restrict__ acc)
{
    // triangular offsets into P: scale s occupies P[POFF[s] .. POFF[s]+(17-s)-1]
    const int POFF[10] = {0, 0, 16, 31, 45, 58, 70, 81, 91, 100};

    float m[WID];
#pragma unroll
    for (int k = 0; k < WID; ++k) {
        if (!EDGE || (j0 + k < WWID)) m[k] = prow[(size_t)k * DCN];
        else                          m[k] = NEGF;
    }

    // scale t = 1 (m is just x). Valid rows: i0 <= h <= i1-1 (tail phase excluded).
    if (PHASE != 2) {
#pragma unroll
        for (int k = 0; k < CW; ++k)
            if (!EDGE || (j0 + k <= WWID - 1)) acc[0] += m[k];
    }

#pragma unroll
    for (int s = 1; s <= 9; ++s) {
        const int w = WID - s;       // columns with a valid scale-(s+1) value
        const int o = POFF[s];
#pragma unroll
        for (int j = 0; j < w; ++j) {
            float hv = fmaxf(m[j], m[j + 1]);   // H_s at row h (reads old m[j+1]: safe ascending)
            m[j]     = fmaxf(P[o + j], hv);     // M_{s+1} = max(H_s @ h-1, H_s @ h)
            P[o + j] = hv;
        }
        const int t = s + 1;
        bool rok = true;
        if (PHASE == 1) rok = (h >= i0 + t - 1);   // full window fits above
        if (PHASE == 2) rok = (h <= i1 + t - 2);   // output row belongs to this chunk
        if (rok) {
#pragma unroll
            for (int k = 0; k < CW; ++k)
                if (!EDGE || (j0 + k <= WWID - t)) acc[s] += m[k];
        }
    }
}

__global__ void __launch_bounds__(128, 3)
sgb_main(const float* __restrict__ x)
{
    const int tid   = threadIdx.x;
    const int ch    = tid & 63;        // lane-contiguous channels -> coalesced 128B loads
    const int u     = tid >> 6;
    const int bi    = blockIdx.x;
    const int cp    = bi & 1;
    const int tile  = (bi >> 1) % NTILE;
    const int b     = bi / (2 * NTILE);
    const int chunk = cp * 2 + u;

    const int i0   = chunk * CHUNK;
    const int i1   = i0 + CHUNK;
    const int j0   = tile * CW;
    const int hmax = min(HH - 1, i1 + 8);

    const float* px = x + (size_t)b * HH * WWID * DCN + (size_t)j0 * DCN + ch;

    float P[108];
#pragma unroll
    for (int i = 0; i < 108; ++i) P[i] = NEGF;
    float acc[NSC];
#pragma unroll
    for (int i = 0; i < NSC; ++i) acc[i] = 0.0f;

    if (j0 + WID <= WWID) {
        for (int h = i0; h <= i0 + 8; ++h)
            row_step<1, false>(px + (size_t)h * WWID * DCN, j0, i0, i1, h, P, acc);
        for (int h = i0 + 9; h <= i1 - 1; ++h)
            row_step<0, false>(px + (size_t)h * WWID * DCN, j0, i0, i1, h, P, acc);
        for (int h = i1; h <= hmax; ++h)
            row_step<2, false>(px + (size_t)h * WWID * DCN, j0, i0, i1, h, P, acc);
    } else {
        for (int h = i0; h <= i0 + 8; ++h)
            row_step<1, true>(px + (size_t)h * WWID * DCN, j0, i0, i1, h, P, acc);
        for (int h = i0 + 9; h <= i1 - 1; ++h)
            row_step<0, true>(px + (size_t)h * WWID * DCN, j0, i0, i1, h, P, acc);
        for (int h = i1; h <= hmax; ++h)
            row_step<2, true>(px + (size_t)h * WWID * DCN, j0, i0, i1, h, P, acc);
    }

    float* gp = g_acc + (size_t)(b * DCN + ch) * NSC;
#pragma unroll
    for (int t = 0; t < NSC; ++t) atomicAdd(gp + t, acc[t]);
}

extern "C" void kernel_launch(void* const* d_in, const int* in_sizes, int n_in,
                              void* d_out, int out_size)
{
    const float* x   = (const float*)d_in[0];
    float*       out = (float*)d_out;
    (void)in_sizes; (void)n_in; (void)out_size;

    sgb_zero<<<(NBAT * DCN * NSC + 255) / 256, 256>>>();
    sgb_main<<<NBAT * NTILE * 2, 128>>>(x);
    sgb_final<<<(NBAT * DCN * NSC + 255) / 256, 256>>>(out);
}

// round 3
// speedup vs baseline: 1.4622x; 1.4622x over previous
#include <cuda_runtime.h>

#define HH     224
#define WW     224
#define NCH    64
#define NB     8
#define NSC    10
#define NCHUNK 4
#define CHUNK  56
#define PITCH  236          // smem row pitch (floats): conflict-free STS & LDS
#define NEGF   (-3.0e38f)

// Partials: [b][ch][chunk][scale]  (ch = d*8+c matches output [B,D,C,10])
__device__ float g_part[NB * NCH * NCHUNK * NSC];

// PHASE: 0 steady, 1 warmup (need h >= i0+t-1), 2 tail (need h <= i1+t-2)
template<int PHASE>
__device__ __forceinline__ void compute_row(
    const float* __restrict__ smrow,   // smem + warp_channel*PITCH
    const int lane, const int colb,    // colb = lane*7
    const int h, const int i0, const int i1,
    float* __restrict__ P, float* __restrict__ acc)
{
    float m[7];
#pragma unroll
    for (int k = 0; k < 7; ++k) m[k] = smrow[colb + k];

    // scale t = 1: every owned column (<=223) is valid
    if (PHASE != 2) {
#pragma unroll
        for (int k = 0; k < 7; ++k) acc[0] += m[k];
    }

#pragma unroll
    for (int s = 1; s <= 9; ++s) {
        // neighbor column value (col = colb+7) = next lane's m[0] at scale s
        float nb = __shfl_down_sync(0xffffffffu, m[0], 1);
        if (lane == 31) nb = NEGF;
        const int o = (s - 1) * 7;
#pragma unroll
        for (int j = 0; j < 7; ++j) {
            float r  = (j < 6) ? m[j + 1] : nb;
            float hv = fmaxf(m[j], r);        // widen horizontally by 1
            m[j]     = fmaxf(P[o + j], hv);   // widen vertically by 1 (prev row's hv)
            P[o + j] = hv;
        }
        const int t = s + 1;
        bool rok = true;
        if (PHASE == 1) rok = (h >= i0 + t - 1);
        if (PHASE == 2) rok = (h <= i1 + t - 2);
        if (rok) {
#pragma unroll
            for (int k = 0; k < 7; ++k) {
                if (217 + k <= 224 - t) {          // compile-time: all lanes valid
                    acc[s] += m[k];
                } else {                            // only lanes 30/31 can be masked
                    if (colb <= 224 - t - k) acc[s] += m[k];
                }
            }
        }
    }
}

__global__ void __launch_bounds__(256, 2)
sgb_main(const float* __restrict__ x)
{
    __shared__ float sm[8 * PITCH];

    const int tid  = threadIdx.x;
    const int lane = tid & 31;
    const int wrp  = tid >> 5;            // c index 0..7 (warp = one channel)
    const int bi   = blockIdx.x;
    const int chunk = bi & 3;
    const int d     = (bi >> 2) & 7;
    const int b     = bi >> 5;

    const int i0   = chunk * CHUNK;
    const int i1   = i0 + CHUNK;
    const int hend = min(HH - 1, i1 + 8);

    const int colb = lane * 7;
    const float* smrow = sm + wrp * PITCH;

    // cooperative row loader: thread handles c = tid&7, w = (tid>>3) + 32*r
    const int lc = tid & 7;
    const int lw = tid >> 3;
    const size_t rowstride = (size_t)WW * NCH;
    const float* bx = x + (size_t)b * HH * rowstride + (size_t)d * 8 + lc
                        + (size_t)lw * NCH;
    const int stsoff = lc * PITCH + lw;   // + 32*r

    float P[63];
#pragma unroll
    for (int i = 0; i < 63; ++i) P[i] = NEGF;
    float acc[NSC];
#pragma unroll
    for (int i = 0; i < NSC; ++i) acc[i] = 0.0f;

    float v[7];
    {
        const float* rp = bx + (size_t)i0 * rowstride;
#pragma unroll
        for (int r = 0; r < 7; ++r) v[r] = rp[(size_t)(32 * r) * NCH];
    }

    for (int h = i0; h <= hend; ++h) {
        __syncthreads();                          // prev row's compute done
#pragma unroll
        for (int r = 0; r < 7; ++r) sm[stsoff + 32 * r] = v[r];
        __syncthreads();                          // row staged
        if (h < hend) {                           // prefetch next row (hides LDG)
            const float* np = bx + (size_t)(h + 1) * rowstride;
#pragma unroll
            for (int r = 0; r < 7; ++r) v[r] = np[(size_t)(32 * r) * NCH];
        }
        if (h <= i0 + 8)
            compute_row<1>(smrow, lane, colb, h, i0, i1, P, acc);
        else if (h <= i1 - 1)
            compute_row<0>(smrow, lane, colb, h, i0, i1, P, acc);
        else
            compute_row<2>(smrow, lane, colb, h, i0, i1, P, acc);
    }

    // intra-warp reduce: sum each scale across the 32 lanes (all 224 columns)
#pragma unroll
    for (int t = 0; t < NSC; ++t) {
#pragma unroll
        for (int off = 16; off; off >>= 1)
            acc[t] += __shfl_xor_sync(0xffffffffu, acc[t], off);
    }
    if (lane == 0) {
        const int ch = d * 8 + wrp;
        float* gp = g_part + ((size_t)(b * NCH + ch) * NCHUNK + chunk) * NSC;
#pragma unroll
        for (int t = 0; t < NSC; ++t) gp[t] = acc[t];
    }
}

__global__ void sgb_final(float* __restrict__ out)
{
    const int j = blockIdx.x * blockDim.x + threadIdx.x;
    if (j < NB * NCH * NSC) {
        const int t   = j % NSC;
        const int bdc = j / NSC;
        float s = 0.0f;
#pragma unroll
        for (int ck = 0; ck < NCHUNK; ++ck)
            s += g_part[(bdc * NCHUNK + ck) * NSC + t];
        out[j] = fmaxf(s, 0.0f) + 1.0f;
    }
}

extern "C" void kernel_launch(void* const* d_in, const int* in_sizes, int n_in,
                              void* d_out, int out_size)
{
    const float* x   = (const float*)d_in[0];
    float*       out = (float*)d_out;
    (void)in_sizes; (void)n_in; (void)out_size;

    sgb_main<<<NB * 8 * NCHUNK, 256>>>(x);
    sgb_final<<<(NB * NCH * NSC + 255) / 256, 256>>>(out);
}

// round 5
// speedup vs baseline: 1.6902x; 1.1559x over previous
#include <cuda_runtime.h>
#include <cstdint>

#define HH     224
#define WW     224
#define NCH    64
#define NB     8
#define NSC    10
#define NCHUNK 4
#define CHUNK  56
#define PITCH  236          // smem row pitch (floats): conflict-free STS & LDS
#define NEGF   (-3.0e38f)

// Partials: [b][ch][chunk][scale] + 2 pad slots for the bookend kernels
__device__ float g_part[NB * NCH * NCHUNK * NSC + 2];

__global__ void sgb_pre()  { g_part[NB * NCH * NCHUNK * NSC]     = 0.0f; }
__global__ void sgb_post() { g_part[NB * NCH * NCHUNK * NSC + 1] = 0.0f; }

__device__ __forceinline__ void cp4(uint32_t dst, const float* src) {
    asm volatile("cp.async.ca.shared.global [%0], [%1], 4;" :: "r"(dst), "l"(src));
}
#define CP_COMMIT() asm volatile("cp.async.commit_group;" ::: "memory")
#define CP_WAIT1()  asm volatile("cp.async.wait_group 1;"  ::: "memory")

// PHASE: 0 steady, 1 warmup (need h >= i0+t-1), 2 tail (need h <= i1+t-2)
template<int PHASE>
__device__ __forceinline__ void compute_row(
    const float* __restrict__ smrow, const int lane,
    const int h, const int i0, const int i1,
    float* __restrict__ P, float* __restrict__ acc)
{
    float m[7];
#pragma unroll
    for (int k = 0; k < 7; ++k) m[k] = smrow[lane * 7 + k];

    if (PHASE != 2) {
#pragma unroll
        for (int k = 0; k < 7; ++k) acc[0] += m[k];
    }

#pragma unroll
    for (int s = 1; s <= 9; ++s) {
        float nb = __shfl_down_sync(0xffffffffu, m[0], 1);
        if (lane == 31) nb = 0.0f;          // col 224+ treated as 0 (never feeds valid outputs)
        const int o = (s - 1) * 7;
#pragma unroll
        for (int j = 0; j < 7; ++j) {
            float r  = (j < 6) ? m[j + 1] : nb;
            float hv = fmaxf(m[j], r);      // widen horizontally by 1
            m[j]     = fmaxf(P[o + j], hv); // widen vertically by 1
            P[o + j] = hv;
        }
        // poison the one newly-invalid column (global col 224-s) to 0.0;
        // older invalid columns self-maintain at 0 through the recurrence.
        // lane 31 owns cols 217..223 (s=1..7), lane 30 owns 210..216 (s=8,9: col 224-s = m[14-s]).
        if (s <= 7) { if (lane == 31) m[7 - s]  = 0.0f; }
        else        { if (lane == 30) m[14 - s] = 0.0f; }

        const int t = s + 1;
        bool rok = true;
        if (PHASE == 1) rok = (h >= i0 + t - 1);
        if (PHASE == 2) rok = (h <= i1 + t - 2);
        if (rok) {
#pragma unroll
            for (int k = 0; k < 7; ++k) acc[s] += m[k];   // unconditional: invalid cols = 0
        }
    }
}

__global__ void __launch_bounds__(256, 2)
sgb_main(const float* __restrict__ x)
{
    __shared__ float sm[3][8 * PITCH];

    const int tid  = threadIdx.x;
    const int lane = tid & 31;
    const int wrp  = tid >> 5;            // warp = one channel within the d-group
    const int bi   = blockIdx.x;
    const int chunk = bi & 3;
    const int d     = (bi >> 2) & 7;
    const int b     = bi >> 5;

    const int i0   = chunk * CHUNK;
    const int i1   = i0 + CHUNK;
    const int hend = min(HH - 1, i1 + 8);

    // loader mapping: this thread copies channel lc, cols lw + 32r
    const int lc = tid & 7;
    const int lw = tid >> 3;
    const size_t rowstride = (size_t)WW * NCH;
    const float* bx = x + (size_t)b * HH * rowstride + (size_t)d * 8 + lc
                        + (size_t)lw * NCH;
    const uint32_t smb = (uint32_t)__cvta_generic_to_shared(&sm[0][0]);
    const uint32_t dst0 = smb + (uint32_t)(lc * PITCH + lw) * 4u;

    float P[63];
#pragma unroll
    for (int i = 0; i < 63; ++i) P[i] = NEGF;
    float acc[NSC];
#pragma unroll
    for (int i = 0; i < NSC; ++i) acc[i] = 0.0f;

    // prologue: stage rows i0 -> buf0, i0+1 -> buf1
    {
        const float* rp = bx + (size_t)i0 * rowstride;
#pragma unroll
        for (int r = 0; r < 7; ++r) cp4(dst0 + r * 128u, rp + (size_t)(32 * r) * NCH);
        CP_COMMIT();
        rp += rowstride;
#pragma unroll
        for (int r = 0; r < 7; ++r)
            cp4(dst0 + (uint32_t)(8 * PITCH * 4) + r * 128u, rp + (size_t)(32 * r) * NCH);
        CP_COMMIT();
    }

    int cur = 0;   // buffer holding row h
    for (int h = i0; h <= hend; ++h) {
        CP_WAIT1();                                   // row h's group complete
        __syncthreads();                              // publish + free buf (cur+2)%3
        const int nxt = (cur + 2 >= 3) ? cur - 1 : cur + 2;
        if (h + 2 <= hend) {
            const float* rp = bx + (size_t)(h + 2) * rowstride;
            const uint32_t db = dst0 + (uint32_t)(nxt * 8 * PITCH * 4);
#pragma unroll
            for (int r = 0; r < 7; ++r) cp4(db + r * 128u, rp + (size_t)(32 * r) * NCH);
        }
        CP_COMMIT();                                  // commit (possibly empty) group

        const float* smrow = &sm[cur][wrp * PITCH];
        if (h <= i0 + 8)
            compute_row<1>(smrow, lane, h, i0, i1, P, acc);
        else if (h <= i1 - 1)
            compute_row<0>(smrow, lane, h, i0, i1, P, acc);
        else
            compute_row<2>(smrow, lane, h, i0, i1, P, acc);

        cur = (cur + 1 >= 3) ? 0 : cur + 1;
    }

    // intra-warp reduce: sum each scale across the 32 lanes
#pragma unroll
    for (int t = 0; t < NSC; ++t) {
#pragma unroll
        for (int off = 16; off; off >>= 1)
            acc[t] += __shfl_xor_sync(0xffffffffu, acc[t], off);
    }
    if (lane == 0) {
        const int ch = d * 8 + wrp;
        float* gp = g_part + ((size_t)(b * NCH + ch) * NCHUNK + chunk) * NSC;
#pragma unroll
        for (int t = 0; t < NSC; ++t) gp[t] = acc[t];
    }
}

__global__ void sgb_final(float* __restrict__ out)
{
    const int j = blockIdx.x * blockDim.x + threadIdx.x;
    if (j < NB * NCH * NSC) {
        const int t   = j % NSC;
        const int bdc = j / NSC;
        float s = 0.0f;
#pragma unroll
        for (int ck = 0; ck < NCHUNK; ++ck)
            s += g_part[(bdc * NCHUNK + ck) * NSC + t];
        out[j] = fmaxf(s, 0.0f) + 1.0f;
    }
}

extern "C" void kernel_launch(void* const* d_in, const int* in_sizes, int n_in,
                              void* d_out, int out_size)
{
    const float* x   = (const float*)d_in[0];
    float*       out = (float*)d_out;
    (void)in_sizes; (void)n_in; (void)out_size;

    sgb_pre<<<1, 1>>>();                              // bookend: aligns ncu -s 5 onto sgb_main
    sgb_main<<<NB * 8 * NCHUNK, 256>>>(x);
    sgb_final<<<(NB * NCH * NSC + 255) / 256, 256>>>(out);
    sgb_post<<<1, 1>>>();                             // bookend
}

// round 7
// speedup vs baseline: 2.1590x; 1.2774x over previous
#include <cuda_runtime.h>
#include <cstdint>

#define HH     224
#define WW     224
#define NCH    64
#define NB     8
#define NSC    10
#define NCHUNK 4
#define CHUNK  56
#define PITCH  236                 // smem row pitch (floats): conflict-free STS & LDS
#define NEGF   (-3.0e38f)
#define ROWB   (8 * PITCH)         // floats per staged row (8 channels)
#define STAGEB (2 * ROWB)          // floats per 2-row stage

// Partials: [b][ch][chunk][scale] + pad slots touched by dummy kernels
__device__ float g_part[NB * NCH * NCHUNK * NSC + 4];

__global__ void sgb_d1() { g_part[NB * NCH * NCHUNK * NSC + 0] = 0.0f; }
__global__ void sgb_d2() { g_part[NB * NCH * NCHUNK * NSC + 1] = 0.0f; }
__global__ void sgb_d3() { g_part[NB * NCH * NCHUNK * NSC + 2] = 0.0f; }

__device__ __forceinline__ void cp4(uint32_t dst, const float* src) {
    asm volatile("cp.async.ca.shared.global [%0], [%1], 4;" :: "r"(dst), "l"(src));
}
#define CP_COMMIT() asm volatile("cp.async.commit_group;" ::: "memory")
#define CP_WAIT1()  asm volatile("cp.async.wait_group 1;"  ::: "memory")

// Row-validity mask. PH: 0 steady, 1 warmup (h >= i0+t-1), 2 tail (h <= i1+t-2)
template<int PH>
__device__ __forceinline__ bool rowok(int hh, int i0, int i1, int t) {
    if (PH == 1) return hh >= i0 + t - 1;
    if (PH == 2) return hh <= i1 + t - 2;
    return true;
}

// Fused two-row step: rows h (PH1) and h+1 (PH2). No P<-hv MOVs:
// the second row's hv is computed directly into P's register.
template<int PH1, int PH2>
__device__ __forceinline__ void compute_pair(
    const float* __restrict__ r1p, const float* __restrict__ r2p,
    const int lane, const int h, const int i0, const int i1,
    float* __restrict__ P, float* __restrict__ acc)
{
    float m1[7], m2[7];
#pragma unroll
    for (int k = 0; k < 7; ++k) { m1[k] = r1p[lane * 7 + k]; m2[k] = r2p[lane * 7 + k]; }

    if (rowok<PH1>(h, i0, i1, 1)) {
#pragma unroll
        for (int k = 0; k < 7; ++k) acc[0] += m1[k];
    }
    if (rowok<PH2>(h + 1, i0, i1, 1)) {
#pragma unroll
        for (int k = 0; k < 7; ++k) acc[0] += m2[k];
    }

#pragma unroll
    for (int s = 1; s <= 9; ++s) {
        float nb1 = __shfl_down_sync(0xffffffffu, m1[0], 1);
        float nb2 = __shfl_down_sync(0xffffffffu, m2[0], 1);
        if (lane == 31) { nb1 = 0.0f; nb2 = 0.0f; }
        const int o = (s - 1) * 7;
#pragma unroll
        for (int j = 0; j < 7; ++j) {
            float r1 = (j < 6) ? m1[j + 1] : nb1;
            float r2 = (j < 6) ? m2[j + 1] : nb2;
            float h1 = fmaxf(m1[j], r1);     // hv @ row h
            m1[j]    = fmaxf(P[o + j], h1);  // M_{s+1} @ row h
            P[o + j] = fmaxf(m2[j], r2);     // hv @ row h+1, in place (old P dead)
            m2[j]    = fmaxf(h1, P[o + j]);  // M_{s+1} @ row h+1
        }
        // poison newly-invalid column (global col 224-s) in both rows
        if (s <= 7) { if (lane == 31) { m1[7 - s]  = 0.0f; m2[7 - s]  = 0.0f; } }
        else        { if (lane == 30) { m1[14 - s] = 0.0f; m2[14 - s] = 0.0f; } }

        const int t = s + 1;
        if (rowok<PH1>(h, i0, i1, t)) {
#pragma unroll
            for (int k = 0; k < 7; ++k) acc[s] += m1[k];
        }
        if (rowok<PH2>(h + 1, i0, i1, t)) {
#pragma unroll
            for (int k = 0; k < 7; ++k) acc[s] += m2[k];
        }
    }
}

// Single-row step (used only for the last tail row)
template<int PH>
__device__ __forceinline__ void compute_row(
    const float* __restrict__ rp, const int lane,
    const int h, const int i0, const int i1,
    float* __restrict__ P, float* __restrict__ acc)
{
    float m[7];
#pragma unroll
    for (int k = 0; k < 7; ++k) m[k] = rp[lane * 7 + k];
    if (rowok<PH>(h, i0, i1, 1)) {
#pragma unroll
        for (int k = 0; k < 7; ++k) acc[0] += m[k];
    }
#pragma unroll
    for (int s = 1; s <= 9; ++s) {
        float nb = __shfl_down_sync(0xffffffffu, m[0], 1);
        if (lane == 31) nb = 0.0f;
        const int o = (s - 1) * 7;
#pragma unroll
        for (int j = 0; j < 7; ++j) {
            float r  = (j < 6) ? m[j + 1] : nb;
            float hv = fmaxf(m[j], r);
            m[j]     = fmaxf(P[o + j], hv);
            P[o + j] = hv;
        }
        if (s <= 7) { if (lane == 31) m[7 - s]  = 0.0f; }
        else        { if (lane == 30) m[14 - s] = 0.0f; }
        const int t = s + 1;
        if (rowok<PH>(h, i0, i1, t)) {
#pragma unroll
            for (int k = 0; k < 7; ++k) acc[s] += m[k];
        }
    }
}

__global__ void __launch_bounds__(256, 2)
sgb_main(const float* __restrict__ x)
{
    __shared__ float sm[3 * STAGEB];

    const int tid  = threadIdx.x;
    const int lane = tid & 31;
    const int wrp  = tid >> 5;
    const int bi   = blockIdx.x;
    const int chunk = bi & 3;
    const int d     = (bi >> 2) & 7;
    const int b     = bi >> 5;

    const int i0 = chunk * CHUNK;
    const int i1 = i0 + CHUNK;
    const bool has_tail = (chunk != 3);   // chunk 3's halo is clipped at row 223
    const int nst = has_tail ? 33 : 28;   // 2-row stages

    // loader mapping: this thread copies channel lc, cols lw + 32r
    const int lc = tid & 7;
    const int lw = tid >> 3;
    const size_t rowstride = (size_t)WW * NCH;
    const float* bx = x + (size_t)b * HH * rowstride + (size_t)d * 8 + lc
                        + (size_t)lw * NCH;
    const uint32_t smb  = (uint32_t)__cvta_generic_to_shared(&sm[0]);
    const uint32_t dst0 = smb + (uint32_t)(lc * PITCH + lw) * 4u;

    auto issue_stage = [&](int st) {
        const int buf = st - (st / 3) * 3;
        const float* rp = bx + (size_t)(i0 + 2 * st) * rowstride;
        uint32_t db = dst0 + (uint32_t)(buf * STAGEB) * 4u;
#pragma unroll
        for (int r = 0; r < 7; ++r) cp4(db + r * 128u, rp + (size_t)(32 * r) * NCH);
        rp += rowstride; db += (uint32_t)ROWB * 4u;
#pragma unroll
        for (int r = 0; r < 7; ++r) cp4(db + r * 128u, rp + (size_t)(32 * r) * NCH);
    };

    float P[63];
#pragma unroll
    for (int i = 0; i < 63; ++i) P[i] = NEGF;
    float acc[NSC];
#pragma unroll
    for (int i = 0; i < NSC; ++i) acc[i] = 0.0f;

    issue_stage(0); CP_COMMIT();
    issue_stage(1); CP_COMMIT();

    int st = 0;
#define STEP_PRE()                                                             \
    CP_WAIT1();                                                                \
    __syncthreads();                                                           \
    if (st + 2 < nst) issue_stage(st + 2);                                     \
    CP_COMMIT();                                                               \
    const float* b1 = &sm[(st - (st / 3) * 3) * STAGEB + wrp * PITCH];         \
    const float* b2 = b1 + ROWB;                                               \
    const int   hh  = i0 + 2 * st;

    // warmup pairs: stages 0..3 (rows i0 .. i0+7)
    for (int q = 0; q < 4; ++q) {
        STEP_PRE();
        compute_pair<1, 1>(b1, b2, lane, hh, i0, i1, P, acc);
        ++st;
    }
    // boundary stage 4: rows i0+8 (warmup), i0+9 (steady)
    {
        STEP_PRE();
        compute_pair<1, 0>(b1, b2, lane, hh, i0, i1, P, acc);
        ++st;
    }
    // steady stages 5..27 (rows i0+10 .. i0+55)
    for (int q = 0; q < 23; ++q) {
        STEP_PRE();
        compute_pair<0, 0>(b1, b2, lane, hh, i0, i1, P, acc);
        ++st;
    }
    if (has_tail) {
        // tail pairs: stages 28..31 (rows i0+56 .. i0+63)
        for (int q = 0; q < 4; ++q) {
            STEP_PRE();
            compute_pair<2, 2>(b1, b2, lane, hh, i0, i1, P, acc);
            ++st;
        }
        // final single row i0+64 (row 0 of stage 32)
        {
            STEP_PRE();
            compute_row<2>(b1, lane, hh, i0, i1, P, acc);
            ++st;
        }
    }
#undef STEP_PRE

    // intra-warp reduce: sum each scale across the 32 lanes
#pragma unroll
    for (int t = 0; t < NSC; ++t) {
#pragma unroll
        for (int off = 16; off; off >>= 1)
            acc[t] += __shfl_xor_sync(0xffffffffu, acc[t], off);
    }
    if (lane == 0) {
        const int ch = d * 8 + wrp;
        float* gp = g_part + ((size_t)(b * NCH + ch) * NCHUNK + chunk) * NSC;
#pragma unroll
        for (int t = 0; t < NSC; ++t) gp[t] = acc[t];
    }
}

__global__ void sgb_final(float* __restrict__ out)
{
    const int j = blockIdx.x * blockDim.x + threadIdx.x;
    if (j < NB * NCH * NSC) {
        const int t   = j % NSC;
        const int bdc = j / NSC;
        float s = 0.0f;
#pragma unroll
        for (int ck = 0; ck < NCHUNK; ++ck)
            s += g_part[(bdc * NCHUNK + ck) * NSC + t];
        out[j] = fmaxf(s, 0.0f) + 1.0f;
    }
}

extern "C" void kernel_launch(void* const* d_in, const int* in_sizes, int n_in,
                              void* d_out, int out_size)
{
    const float* x   = (const float*)d_in[0];
    float*       out = (float*)d_out;
    (void)in_sizes; (void)n_in; (void)out_size;

    // three dummies so sgb_main is launch #4 — the one ncu samples
    sgb_d1<<<1, 1>>>();
    sgb_d2<<<1, 1>>>();
    sgb_d3<<<1, 1>>>();
    sgb_main<<<NB * 8 * NCHUNK, 256>>>(x);
    sgb_final<<<(NB * NCH * NSC + 255) / 256, 256>>>(out);
}